// round 2
// baseline (speedup 1.0000x reference)
#include <cuda_runtime.h>
#include <math.h>

#define B_ 16
#define S_ 2048
#define E_ 1024
#define H_ 64

// Scratch for projected Q/K/V (8 MB each) — __device__ globals, allocation-free.
__device__ float g_Q[B_ * S_ * H_];
__device__ float g_K[B_ * S_ * H_];
__device__ float g_V[B_ * S_ * H_];

// ---------------------------------------------------------------------------
// QKV projection: out[row, h] = sum_e x[row, e] * W[e, h]
// M = B*S = 32768, K = E = 1024, N = H = 64.
// grid = (M/128, 3), block = 256. blockIdx.y selects {Wq,Wk,Wv} -> {g_Q,g_K,g_V}.
// BM=128, BN=64, BK=32; each thread computes an 8x4 sub-tile.
// ---------------------------------------------------------------------------
__global__ __launch_bounds__(256) void qkv_kernel(
    const float* __restrict__ x, const float* __restrict__ Wq,
    const float* __restrict__ Wk, const float* __restrict__ Wv)
{
    constexpr int BM = 128, BK = 32;
    __shared__ float xs[BM][BK + 1];  // +1 pad: conflict-free column reads
    __shared__ float ws[BK][64];

    const float* __restrict__ W =
        (blockIdx.y == 0) ? Wq : (blockIdx.y == 1 ? Wk : Wv);
    float* outb = (blockIdx.y == 0) ? g_Q : (blockIdx.y == 1 ? g_K : g_V);

    const int tid = threadIdx.x;
    const int tx = tid & 15;   // column group (4 cols)
    const int ty = tid >> 4;   // row group (8 rows)
    const int rbase = blockIdx.x * BM;

    float acc[8][4];
#pragma unroll
    for (int m = 0; m < 8; m++)
#pragma unroll
        for (int n = 0; n < 4; n++) acc[m][n] = 0.f;

    for (int k0 = 0; k0 < E_; k0 += BK) {
        // x tile: 128x32 floats = 1024 float4, 4 per thread (coalesced)
#pragma unroll
        for (int i = 0; i < 4; i++) {
            int fi = tid + i * 256;
            int r = fi >> 3;
            int c = (fi & 7) << 2;
            float4 v = *(const float4*)&x[(size_t)(rbase + r) * E_ + k0 + c];
            xs[r][c + 0] = v.x; xs[r][c + 1] = v.y;
            xs[r][c + 2] = v.z; xs[r][c + 3] = v.w;
        }
        // W tile: 32x64 floats = 512 float4, 2 per thread
#pragma unroll
        for (int i = 0; i < 2; i++) {
            int fi = tid + i * 256;
            int kk = fi >> 4;
            int c = (fi & 15) << 2;
            *(float4*)&ws[kk][c] = *(const float4*)&W[(size_t)(k0 + kk) * H_ + c];
        }
        __syncthreads();

#pragma unroll
        for (int kk = 0; kk < BK; kk++) {
            float a[8];
#pragma unroll
            for (int m = 0; m < 8; m++) a[m] = xs[ty * 8 + m][kk];
            float4 b = *(const float4*)&ws[kk][tx * 4];
#pragma unroll
            for (int m = 0; m < 8; m++) {
                acc[m][0] += a[m] * b.x;
                acc[m][1] += a[m] * b.y;
                acc[m][2] += a[m] * b.z;
                acc[m][3] += a[m] * b.w;
            }
        }
        __syncthreads();
    }

#pragma unroll
    for (int m = 0; m < 8; m++) {
        int r = rbase + ty * 8 + m;
        float4 o = make_float4(acc[m][0], acc[m][1], acc[m][2], acc[m][3]);
        *(float4*)&outb[(size_t)r * H_ + tx * 4] = o;
    }
}

// ---------------------------------------------------------------------------
// Flash-style causal attention.
// grid = (S/64 q-tiles, B), block = 256 threads.
// Thread map: r = tid/4 (query row in tile, 0..63), g = tid%4 (key/dim quarter).
// Each thread owns 16 score columns (keys g*16..g*16+15) and 16 output dims
// (d = g*16..g*16+15). Row stats reduced across the 4 g-threads via shfl.
// Dynamic smem: Qs,Ks,Vs,Ps each [64][68] fp32 (stride 68 -> conflict-free).
// ---------------------------------------------------------------------------
__global__ __launch_bounds__(256) void attn_kernel(float* __restrict__ out)
{
    constexpr int STR = 68;
    extern __shared__ float sm[];
    float* Qs = sm;
    float* Ks = sm + 64 * STR;
    float* Vs = sm + 2 * 64 * STR;
    float* Ps = sm + 3 * 64 * STR;

    const int tid = threadIdx.x;
    const int r = tid >> 2;
    const int g = tid & 3;
    const int qt = blockIdx.x;
    const int b = blockIdx.y;
    const int qbase = qt * 64;

    const float* __restrict__ Qg = g_Q + (size_t)b * S_ * H_;
    const float* __restrict__ Kg = g_K + (size_t)b * S_ * H_;
    const float* __restrict__ Vg = g_V + (size_t)b * S_ * H_;

    // Load Q tile (64x64 fp32 = 1024 float4, 4/thread)
#pragma unroll
    for (int i = 0; i < 4; i++) {
        int fi = tid + i * 256;
        int row = fi >> 4;
        int c = (fi & 15) << 2;
        *(float4*)&Qs[row * STR + c] =
            *(const float4*)&Qg[(size_t)(qbase + row) * H_ + c];
    }

    float m = -1e30f, l = 0.f;
    float acc[16];
#pragma unroll
    for (int j = 0; j < 16; j++) acc[j] = 0.f;

    const float scale = 0.125f;  // 1/sqrt(64)
    const int qrow = qbase + r;

    for (int kt = 0; kt <= qt; kt++) {
        const int kbase = kt * 64;
        __syncthreads();  // prev-iter reads done (also orders Q-tile stores)
#pragma unroll
        for (int i = 0; i < 4; i++) {
            int fi = tid + i * 256;
            int row = fi >> 4;
            int c = (fi & 15) << 2;
            *(float4*)&Ks[row * STR + c] =
                *(const float4*)&Kg[(size_t)(kbase + row) * H_ + c];
            *(float4*)&Vs[row * STR + c] =
                *(const float4*)&Vg[(size_t)(kbase + row) * H_ + c];
        }
        __syncthreads();

        // Scores: s[j] = Q[r,:] . K[g*16+j,:]
        float s[16];
#pragma unroll
        for (int j = 0; j < 16; j++) s[j] = 0.f;
#pragma unroll
        for (int d = 0; d < 64; d += 4) {
            float4 q4 = *(const float4*)&Qs[r * STR + d];
#pragma unroll
            for (int j = 0; j < 16; j++) {
                float4 k4 = *(const float4*)&Ks[(g * 16 + j) * STR + d];
                s[j] += q4.x * k4.x + q4.y * k4.y + q4.z * k4.z + q4.w * k4.w;
            }
        }

        // Causal mask + scale + local max
        float mloc = -1e30f;
#pragma unroll
        for (int j = 0; j < 16; j++) {
            int key = kbase + g * 16 + j;
            s[j] = (key <= qrow) ? s[j] * scale : -1e30f;
            mloc = fmaxf(mloc, s[j]);
        }
        // Row max across the 4 g-threads (adjacent lanes in the warp)
        mloc = fmaxf(mloc, __shfl_xor_sync(0xffffffffu, mloc, 1));
        mloc = fmaxf(mloc, __shfl_xor_sync(0xffffffffu, mloc, 2));
        float mnew = fmaxf(m, mloc);
        float corr = __expf(m - mnew);

        float psum = 0.f;
#pragma unroll
        for (int j = 0; j < 16; j++) {
            float p = __expf(s[j] - mnew);
            s[j] = p;
            psum += p;
        }
        psum += __shfl_xor_sync(0xffffffffu, psum, 1);
        psum += __shfl_xor_sync(0xffffffffu, psum, 2);
        l = l * corr + psum;
        m = mnew;
#pragma unroll
        for (int j = 0; j < 16; j++) acc[j] *= corr;

        // Publish probabilities for the AV stage
#pragma unroll
        for (int j = 0; j < 16; j += 4) {
            float4 p4 = make_float4(s[j], s[j + 1], s[j + 2], s[j + 3]);
            *(float4*)&Ps[r * STR + g * 16 + j] = p4;
        }
        __syncthreads();

        // O[r, g*16+j] += sum_key P[r,key] * V[key, g*16+j]
#pragma unroll 8
        for (int key = 0; key < 64; key++) {
            float p = Ps[r * STR + key];
#pragma unroll
            for (int j = 0; j < 16; j += 4) {
                float4 v4 = *(const float4*)&Vs[key * STR + g * 16 + j];
                acc[j + 0] += p * v4.x;
                acc[j + 1] += p * v4.y;
                acc[j + 2] += p * v4.z;
                acc[j + 3] += p * v4.w;
            }
        }
    }

    const float inv = 1.f / l;
    float* orow = out + ((size_t)b * S_ + qbase + r) * H_ + g * 16;
#pragma unroll
    for (int j = 0; j < 16; j += 4) {
        float4 o = make_float4(acc[j] * inv, acc[j + 1] * inv,
                               acc[j + 2] * inv, acc[j + 3] * inv);
        *(float4*)&orow[j] = o;
    }
}

// ---------------------------------------------------------------------------
extern "C" void kernel_launch(void* const* d_in, const int* in_sizes, int n_in,
                              void* d_out, int out_size)
{
    const float* x  = (const float*)d_in[0];
    const float* Wq = (const float*)d_in[1];
    const float* Wk = (const float*)d_in[2];
    const float* Wv = (const float*)d_in[3];
    float* out = (float*)d_out;
    (void)in_sizes; (void)n_in; (void)out_size;

    // QKV projection: 256 row-tiles x 3 weight matrices
    qkv_kernel<<<dim3(256, 3), 256>>>(x, Wq, Wk, Wv);

    // Attention: 32 query tiles x 16 batches; 68 KB dynamic smem
    const int smem_bytes = 4 * 64 * 68 * (int)sizeof(float);
    cudaFuncSetAttribute(attn_kernel,
                         cudaFuncAttributeMaxDynamicSharedMemorySize,
                         smem_bytes);
    attn_kernel<<<dim3(32, 16), 256, smem_bytes>>>(out);
}

// round 3
// speedup vs baseline: 3.8797x; 3.8797x over previous
#include <cuda_runtime.h>
#include <stdint.h>
#include <math.h>

#define B_ 16
#define S_ 2048
#define E_ 1024
#define H_ 64

// Scratch for projected Q/K/V (8 MB each) — __device__ globals, allocation-free.
__device__ float g_Q[B_ * S_ * H_];
__device__ float g_K[B_ * S_ * H_];
__device__ float g_V[B_ * S_ * H_];

// ---------------------------------------------------------------------------
// TF32 helpers (3xTF32 split: x = hi + lo, products hi*hi + hi*lo + lo*hi)
// ---------------------------------------------------------------------------
__device__ __forceinline__ uint32_t cvt_tf32(float x) {
    uint32_t r;
    asm("cvt.rna.tf32.f32 %0, %1;" : "=r"(r) : "f"(x));
    return r;
}
__device__ __forceinline__ void split_tf32(float x, uint32_t& hi, uint32_t& lo) {
    hi = cvt_tf32(x);
    lo = cvt_tf32(x - __uint_as_float(hi));
}
// D += A(16x8,row) * B(8x8,col);  per-thread frags per PTX m16n8k8 tf32 layout.
__device__ __forceinline__ void mma8(float* d, uint32_t a0, uint32_t a1,
                                     uint32_t a2, uint32_t a3,
                                     uint32_t b0, uint32_t b1) {
    asm volatile(
        "mma.sync.aligned.m16n8k8.row.col.f32.tf32.tf32.f32 "
        "{%0,%1,%2,%3}, {%4,%5,%6,%7}, {%8,%9}, {%0,%1,%2,%3};\n"
        : "+f"(d[0]), "+f"(d[1]), "+f"(d[2]), "+f"(d[3])
        : "r"(a0), "r"(a1), "r"(a2), "r"(a3), "r"(b0), "r"(b1));
}

// ---------------------------------------------------------------------------
// QKV projection with 3xTF32 mma: out[row,h] = sum_e x[row,e] * W[e,h]
// grid=(256,3) block=256 (8 warps). Warp w owns rows [bx*128 + w*16, +16),
// all 64 cols. BK=32 smem tiles.
// xs stride 36 (A-reads bank= 4*gid+tig, CF), ws stride 72 (B-reads 8*tig+gid, CF).
// ---------------------------------------------------------------------------
__global__ __launch_bounds__(256) void qkv_kernel(
    const float* __restrict__ x, const float* __restrict__ Wq,
    const float* __restrict__ Wk, const float* __restrict__ Wv)
{
    constexpr int SX = 36, SW = 72;
    __shared__ float xs[128 * SX];
    __shared__ float ws[32 * SW];

    const float* __restrict__ W =
        (blockIdx.y == 0) ? Wq : (blockIdx.y == 1 ? Wk : Wv);
    float* outb = (blockIdx.y == 0) ? g_Q : (blockIdx.y == 1 ? g_K : g_V);

    const int tid = threadIdx.x;
    const int w   = tid >> 5;
    const int lane = tid & 31;
    const int gid = lane >> 2;   // group (row within frag)
    const int tig = lane & 3;    // thread-in-group (k / col pairs)
    const int rbase = blockIdx.x * 128;

    float acc[8][4];
#pragma unroll
    for (int nt = 0; nt < 8; nt++)
#pragma unroll
        for (int i = 0; i < 4; i++) acc[nt][i] = 0.f;

    for (int k0 = 0; k0 < E_; k0 += 32) {
        // x tile 128x32: 1024 float4, 4/thread
#pragma unroll
        for (int i = 0; i < 4; i++) {
            int fi = tid + i * 256;
            int r = fi >> 3;
            int c = (fi & 7) << 2;
            float4 v = *(const float4*)&x[(size_t)(rbase + r) * E_ + k0 + c];
            *(float4*)&xs[r * SX + c] = v;
        }
        // W tile 32x64: 512 float4, 2/thread
#pragma unroll
        for (int i = 0; i < 2; i++) {
            int fi = tid + i * 256;
            int kk = fi >> 4;
            int c = (fi & 15) << 2;
            *(float4*)&ws[kk * SW + c] = *(const float4*)&W[(size_t)(k0 + kk) * H_ + c];
        }
        __syncthreads();

#pragma unroll
        for (int k8 = 0; k8 < 4; k8++) {
            // A frag (Q-side = x): rows w*16+gid(+8), cols k8*8+tig(+4)
            uint32_t ah[4], al[4];
            split_tf32(xs[(w * 16 + gid) * SX + k8 * 8 + tig],     ah[0], al[0]);
            split_tf32(xs[(w * 16 + gid + 8) * SX + k8 * 8 + tig], ah[1], al[1]);
            split_tf32(xs[(w * 16 + gid) * SX + k8 * 8 + tig + 4],     ah[2], al[2]);
            split_tf32(xs[(w * 16 + gid + 8) * SX + k8 * 8 + tig + 4], al[3], al[3]);
            // fix typo-safe: recompute a3 hi properly
            split_tf32(xs[(w * 16 + gid + 8) * SX + k8 * 8 + tig + 4], ah[3], al[3]);
#pragma unroll
            for (int nt = 0; nt < 8; nt++) {
                uint32_t bh0, bl0, bh1, bl1;
                split_tf32(ws[(k8 * 8 + tig) * SW + nt * 8 + gid],     bh0, bl0);
                split_tf32(ws[(k8 * 8 + tig + 4) * SW + nt * 8 + gid], bh1, bl1);
                mma8(acc[nt], ah[0], ah[1], ah[2], ah[3], bh0, bh1);
                mma8(acc[nt], ah[0], ah[1], ah[2], ah[3], bl0, bl1);
                mma8(acc[nt], al[0], al[1], al[2], al[3], bh0, bh1);
            }
        }
        __syncthreads();
    }

    const int r0 = rbase + w * 16 + gid;
#pragma unroll
    for (int nt = 0; nt < 8; nt++) {
        int c = nt * 8 + 2 * tig;
        *(float2*)&outb[(size_t)r0 * H_ + c] = make_float2(acc[nt][0], acc[nt][1]);
        *(float2*)&outb[(size_t)(r0 + 8) * H_ + c] = make_float2(acc[nt][2], acc[nt][3]);
    }
}

// ---------------------------------------------------------------------------
// Flash attention with 3xTF32 mma.
// grid=(16 qtiles reversed, 16 batches), block=256 (8 warps).
// Q-tile = 128 rows; warp w owns rows qbase + w*16 .. +16.
// Key tiles of 64. S = Q*K^T via mma (Q pre-scaled by 0.125), online softmax
// in accumulator layout, P -> per-warp smem -> A-frags for PV mma.
// Strides: Qs/Ks/Ps 68 (A-pattern CF), Vs 72 (B-pattern CF).
// ---------------------------------------------------------------------------
__global__ __launch_bounds__(256, 2) void attn_kernel(float* __restrict__ out)
{
    constexpr int SQ = 68, SK = 68, SV = 72, SP = 68;
    extern __shared__ float sm[];
    float* Qs = sm;                       // 128 x 68
    float* Ks = Qs + 128 * SQ;            // 64 x 68
    float* Vs = Ks + 64 * SK;             // 64 x 72
    float* Ps = Vs + 64 * SV;             // 128 x 68

    const int tid = threadIdx.x;
    const int w = tid >> 5;
    const int lane = tid & 31;
    const int gid = lane >> 2;
    const int tig = lane & 3;

    const int qt = (int)gridDim.x - 1 - (int)blockIdx.x;  // heavy tiles first
    const int b = blockIdx.y;
    const int qbase = qt * 128;

    const float* __restrict__ Qg = g_Q + (size_t)b * S_ * H_;
    const float* __restrict__ Kg = g_K + (size_t)b * S_ * H_;
    const float* __restrict__ Vg = g_V + (size_t)b * S_ * H_;

    // Load Q tile (128x64), pre-scaled by 1/sqrt(H)=0.125
#pragma unroll
    for (int i = 0; i < 8; i++) {
        int fi = tid + i * 256;
        int r = fi >> 4;
        int c = (fi & 15) << 2;
        float4 v = *(const float4*)&Qg[(size_t)(qbase + r) * H_ + c];
        v.x *= 0.125f; v.y *= 0.125f; v.z *= 0.125f; v.w *= 0.125f;
        *(float4*)&Qs[r * SQ + c] = v;
    }

    float o[8][4];
#pragma unroll
    for (int nt = 0; nt < 8; nt++)
#pragma unroll
        for (int i = 0; i < 4; i++) o[nt][i] = 0.f;
    float m0 = -1e30f, m1 = -1e30f, l0 = 0.f, l1 = 0.f;

    const int row0 = qbase + w * 16 + gid;
    const int row1 = row0 + 8;
    const int nkt = 2 * qt + 2;

    for (int kt = 0; kt < nkt; kt++) {
        const int kbase = kt * 64;
        __syncthreads();  // protect K/V overwrite vs prev-iter reads (also Q 1st iter)
#pragma unroll
        for (int i = 0; i < 4; i++) {
            int fi = tid + i * 256;
            int r = fi >> 4;
            int c = (fi & 15) << 2;
            *(float4*)&Ks[r * SK + c] = *(const float4*)&Kg[(size_t)(kbase + r) * H_ + c];
            *(float4*)&Vs[r * SV + c] = *(const float4*)&Vg[(size_t)(kbase + r) * H_ + c];
        }
        __syncthreads();

        // ---- S = Q K^T (16 x 64 per warp), 3xTF32 ----
        float s[8][4];
#pragma unroll
        for (int nt = 0; nt < 8; nt++)
#pragma unroll
            for (int i = 0; i < 4; i++) s[nt][i] = 0.f;

#pragma unroll
        for (int k8 = 0; k8 < 8; k8++) {
            uint32_t ah[4], al[4];
            split_tf32(Qs[(w * 16 + gid) * SQ + k8 * 8 + tig],         ah[0], al[0]);
            split_tf32(Qs[(w * 16 + gid + 8) * SQ + k8 * 8 + tig],     ah[1], al[1]);
            split_tf32(Qs[(w * 16 + gid) * SQ + k8 * 8 + tig + 4],     ah[2], al[2]);
            split_tf32(Qs[(w * 16 + gid + 8) * SQ + k8 * 8 + tig + 4], ah[3], al[3]);
#pragma unroll
            for (int nt = 0; nt < 8; nt++) {
                uint32_t bh0, bl0, bh1, bl1;
                split_tf32(Ks[(nt * 8 + gid) * SK + k8 * 8 + tig],     bh0, bl0);
                split_tf32(Ks[(nt * 8 + gid) * SK + k8 * 8 + tig + 4], bh1, bl1);
                mma8(s[nt], ah[0], ah[1], ah[2], ah[3], bh0, bh1);
                mma8(s[nt], ah[0], ah[1], ah[2], ah[3], bl0, bl1);
                mma8(s[nt], al[0], al[1], al[2], al[3], bh0, bh1);
            }
        }

        // ---- causal mask + online softmax (rows gid, gid+8) ----
        float mloc0 = -1e30f, mloc1 = -1e30f;
#pragma unroll
        for (int nt = 0; nt < 8; nt++) {
            int c0 = kbase + nt * 8 + 2 * tig;
            int c1 = c0 + 1;
            s[nt][0] = (c0 <= row0) ? s[nt][0] : -1e30f;
            s[nt][1] = (c1 <= row0) ? s[nt][1] : -1e30f;
            s[nt][2] = (c0 <= row1) ? s[nt][2] : -1e30f;
            s[nt][3] = (c1 <= row1) ? s[nt][3] : -1e30f;
            mloc0 = fmaxf(mloc0, fmaxf(s[nt][0], s[nt][1]));
            mloc1 = fmaxf(mloc1, fmaxf(s[nt][2], s[nt][3]));
        }
        mloc0 = fmaxf(mloc0, __shfl_xor_sync(0xffffffffu, mloc0, 1));
        mloc0 = fmaxf(mloc0, __shfl_xor_sync(0xffffffffu, mloc0, 2));
        mloc1 = fmaxf(mloc1, __shfl_xor_sync(0xffffffffu, mloc1, 1));
        mloc1 = fmaxf(mloc1, __shfl_xor_sync(0xffffffffu, mloc1, 2));

        float mn0 = fmaxf(m0, mloc0);
        float mn1 = fmaxf(m1, mloc1);
        float corr0 = __expf(m0 - mn0);
        float corr1 = __expf(m1 - mn1);
        m0 = mn0; m1 = mn1;

        float ps0 = 0.f, ps1 = 0.f;
#pragma unroll
        for (int nt = 0; nt < 8; nt++) {
            s[nt][0] = __expf(s[nt][0] - mn0);
            s[nt][1] = __expf(s[nt][1] - mn0);
            s[nt][2] = __expf(s[nt][2] - mn1);
            s[nt][3] = __expf(s[nt][3] - mn1);
            ps0 += s[nt][0] + s[nt][1];
            ps1 += s[nt][2] + s[nt][3];
        }
        ps0 += __shfl_xor_sync(0xffffffffu, ps0, 1);
        ps0 += __shfl_xor_sync(0xffffffffu, ps0, 2);
        ps1 += __shfl_xor_sync(0xffffffffu, ps1, 1);
        ps1 += __shfl_xor_sync(0xffffffffu, ps1, 2);
        l0 = l0 * corr0 + ps0;
        l1 = l1 * corr1 + ps1;

#pragma unroll
        for (int nt = 0; nt < 8; nt++) {
            o[nt][0] *= corr0; o[nt][1] *= corr0;
            o[nt][2] *= corr1; o[nt][3] *= corr1;
        }

        // ---- P -> per-warp smem (accum layout -> A layout) ----
        __syncwarp();
#pragma unroll
        for (int nt = 0; nt < 8; nt++) {
            int c = nt * 8 + 2 * tig;
            *(float2*)&Ps[(w * 16 + gid) * SP + c] = make_float2(s[nt][0], s[nt][1]);
            *(float2*)&Ps[(w * 16 + gid + 8) * SP + c] = make_float2(s[nt][2], s[nt][3]);
        }
        __syncwarp();

        // ---- O += P V (16 x 64 per warp over k=64 keys), 3xTF32 ----
#pragma unroll
        for (int k8 = 0; k8 < 8; k8++) {
            uint32_t ah[4], al[4];
            split_tf32(Ps[(w * 16 + gid) * SP + k8 * 8 + tig],         ah[0], al[0]);
            split_tf32(Ps[(w * 16 + gid + 8) * SP + k8 * 8 + tig],     ah[1], al[1]);
            split_tf32(Ps[(w * 16 + gid) * SP + k8 * 8 + tig + 4],     ah[2], al[2]);
            split_tf32(Ps[(w * 16 + gid + 8) * SP + k8 * 8 + tig + 4], ah[3], al[3]);
#pragma unroll
            for (int nt = 0; nt < 8; nt++) {
                uint32_t bh0, bl0, bh1, bl1;
                split_tf32(Vs[(k8 * 8 + tig) * SV + nt * 8 + gid],     bh0, bl0);
                split_tf32(Vs[(k8 * 8 + tig + 4) * SV + nt * 8 + gid], bh1, bl1);
                mma8(o[nt], ah[0], ah[1], ah[2], ah[3], bh0, bh1);
                mma8(o[nt], ah[0], ah[1], ah[2], ah[3], bl0, bl1);
                mma8(o[nt], al[0], al[1], al[2], al[3], bh0, bh1);
            }
        }
    }

    const float inv0 = 1.f / l0;
    const float inv1 = 1.f / l1;
#pragma unroll
    for (int nt = 0; nt < 8; nt++) {
        int c = nt * 8 + 2 * tig;
        *(float2*)&out[(size_t)((size_t)b * S_ + row0) * H_ + c] =
            make_float2(o[nt][0] * inv0, o[nt][1] * inv0);
        *(float2*)&out[(size_t)((size_t)b * S_ + row1) * H_ + c] =
            make_float2(o[nt][2] * inv1, o[nt][3] * inv1);
    }
}

// ---------------------------------------------------------------------------
extern "C" void kernel_launch(void* const* d_in, const int* in_sizes, int n_in,
                              void* d_out, int out_size)
{
    const float* x  = (const float*)d_in[0];
    const float* Wq = (const float*)d_in[1];
    const float* Wk = (const float*)d_in[2];
    const float* Wv = (const float*)d_in[3];
    float* out = (float*)d_out;
    (void)in_sizes; (void)n_in; (void)out_size;

    qkv_kernel<<<dim3(256, 3), 256>>>(x, Wq, Wk, Wv);

    const int smem_bytes = (128 * 68 + 64 * 68 + 64 * 72 + 128 * 68) * (int)sizeof(float);
    cudaFuncSetAttribute(attn_kernel,
                         cudaFuncAttributeMaxDynamicSharedMemorySize,
                         smem_bytes);
    attn_kernel<<<dim3(16, 16), 256, smem_bytes>>>(out);
}